// round 13
// baseline (speedup 1.0000x reference)
#include <cuda_runtime.h>
#include <math.h>

#define BB 32
#define TT 512
#define FF 128
#define RR 2048
#define C1 0.05f
#define C2 0.95f

#define NCTA 128
#define ROWS_PER_CTA 16
#define NTHREADS 256
#define NCHUNK 8
#define WQ_STRIDE 513   // W row stride in float4 (2052 floats)
#define SQ_STRIDE 65    // s chunk row stride in float4 (260 floats)

__device__ float g_state[2][BB * RR];
__device__ unsigned int g_bar;

// ---------------------------------------------------------------------------
// IDENTIFIED REFERENCE RECIPE (decoded round 12):
//   gemm: fp32 splitK=4 — 4 k-slices of 512 floats; each slice a serial FMA
//         chain from zero, k ascending; slice partials folded by ascending
//         fp32 adds.
//   z   : __fadd_rn(acc, u)
//   tanh: XLA EmitFastTanh — |x|<0.0004 -> x; clamp ±7.99881172180175781;
//         FMA-contracted Cephes rational; IEEE divide.
//   upd : fmaf(C1, s, __fmul_rn(C2, th))
//   u   : serial FMA chain over f ascending (K=128) + bias (fadd).
// ---------------------------------------------------------------------------

__device__ __forceinline__ float fast_tanh_B(float x) {
    const float cl = 7.99881172180175781f;
    float xc = fminf(fmaxf(x, -cl), cl);
    float x2 = __fmul_rn(xc, xc);
    float p = -2.76076847742355e-16f;
    p = fmaf(x2, p, 2.00018790482477e-13f);
    p = fmaf(x2, p, -8.60467152213735e-11f);
    p = fmaf(x2, p, 5.12229709037114e-08f);
    p = fmaf(x2, p, 1.48572235717979e-05f);
    p = fmaf(x2, p, 6.37261928875436e-04f);
    p = fmaf(x2, p, 4.89352455891786e-03f);
    float num = __fmul_rn(xc, p);
    float q = 1.19825839466702e-06f;
    q = fmaf(x2, q, 1.18534705686654e-04f);
    q = fmaf(x2, q, 2.26843463243900e-03f);
    q = fmaf(x2, q, 4.89352518554385e-03f);
    float r = __fdiv_rn(num, q);
    return (fabsf(x) < 0.0004f) ? x : r;
}
__device__ __forceinline__ float do_upd(float s, float th) {
    return fmaf(C1, s, __fmul_rn(C2, th));
}

// ---------------------------------------------------------------------------
__global__ void init_kernel(const float* __restrict__ state0) {
    int i = blockIdx.x * blockDim.x + threadIdx.x;
    if (i == 0) g_bar = 0u;
    if (i < BB * RR) g_state[0][i] = state0[i & (RR - 1)];
}

// ---------------------------------------------------------------------------
// u[bt][r] = serial FMA chain over f ascending (K=128) + b[r].
// ---------------------------------------------------------------------------
#define XS_STRIDE 33
#define WS_STRIDE4 33

__global__ void __launch_bounds__(256) input_gemm_strict(
    const float* __restrict__ x, const float* __restrict__ Win,
    const float* __restrict__ bias, float* __restrict__ out) {
    extern __shared__ float sm[];
    float4* xs4 = reinterpret_cast<float4*>(sm);
    float4* ws4 = reinterpret_cast<float4*>(sm) + 32 * XS_STRIDE;

    const int tid = threadIdx.x;
    const int bt0 = blockIdx.x * 32;

    const float4* xg4 = reinterpret_cast<const float4*>(x);
    #pragma unroll
    for (int it = 0; it < 4; ++it) {
        int L = it * 256 + tid;
        int row = L >> 5, c = L & 31;
        xs4[row * XS_STRIDE + c] = xg4[(size_t)(bt0 + row) * 32 + c];
    }

    const int btl = tid >> 3;
    const int rg = tid & 7;
    const float4* wg4 = reinterpret_cast<const float4*>(Win);

    for (int rt = 0; rt < RR; rt += 64) {
        __syncthreads();
        #pragma unroll
        for (int it = 0; it < 8; ++it) {
            int L = it * 256 + tid;
            int row = L >> 5, c = L & 31;
            ws4[row * WS_STRIDE4 + c] = wg4[(size_t)(rt + row) * 32 + c];
        }
        __syncthreads();

        float acc[8];
        #pragma unroll
        for (int j = 0; j < 8; ++j) acc[j] = 0.0f;

        #pragma unroll 8
        for (int fq = 0; fq < 32; ++fq) {
            float4 xq = xs4[btl * XS_STRIDE + fq];
            #pragma unroll
            for (int j = 0; j < 8; ++j) {
                float4 wq = ws4[(rg * 8 + j) * WS_STRIDE4 + fq];
                float a = acc[j];
                a = fmaf(xq.x, wq.x, a);
                a = fmaf(xq.y, wq.y, a);
                a = fmaf(xq.z, wq.z, a);
                a = fmaf(xq.w, wq.w, a);
                acc[j] = a;
            }
        }
        #pragma unroll
        for (int j = 0; j < 8; ++j) {
            int r = rt + rg * 8 + j;
            out[(size_t)(bt0 + btl) * RR + r] = __fadd_rn(acc[j], bias[r]);
        }
    }
}

// ---------------------------------------------------------------------------
// Persistent recurrent kernel. Thread t: row r_loc = t>>4, batches bA = t&15,
// bB = bA+16 (2 outputs, ILP=2). Slice = 512 floats = 2 staging chunks; fold
// the running slice partial into acc at every odd-chunk boundary.
// ---------------------------------------------------------------------------
__global__ void __launch_bounds__(NTHREADS) recurrent_kernel(
    const float* __restrict__ Wrec, float* __restrict__ out) {
    extern __shared__ float sm[];
    float4* wsm4 = reinterpret_cast<float4*>(sm);
    float4* ssm4 = reinterpret_cast<float4*>(sm) + ROWS_PER_CTA * WQ_STRIDE;

    const int tid = threadIdx.x;
    const int cta = blockIdx.x;
    const int rbase = cta * ROWS_PER_CTA;

    const float4* W4 = reinterpret_cast<const float4*>(Wrec);
    for (int L = tid; L < ROWS_PER_CTA * (RR / 4); L += NTHREADS) {
        int row = L >> 9;
        int c = L & 511;
        wsm4[row * WQ_STRIDE + c] = W4[(size_t)(rbase + row) * (RR / 4) + c];
    }

    const int r_loc = tid >> 4;
    const int bA = tid & 15;       // 0..15
    const int bB = bA + 16;        // 16..31
    const int r = rbase + r_loc;

    __syncthreads();

    int par = 0;
    for (int t = 0; t < TT; ++t) {
        const float* scur = g_state[par];
        float* snxt = g_state[par ^ 1];
        const float4* s4g = reinterpret_cast<const float4*>(scur);

        size_t oA = ((size_t)bA * TT + t) * RR + r;
        size_t oB = ((size_t)bB * TT + t) * RR + r;
        float uA = out[oA];
        float uB = out[oB];
        float soA = __ldcg(&scur[bA * RR + r]);
        float soB = __ldcg(&scur[bB * RR + r]);

        float accA = 0.0f, accB = 0.0f;   // folded slice partials
        float pA = 0.0f, pB = 0.0f;       // current slice chains

        #pragma unroll
        for (int ch = 0; ch < NCHUNK; ++ch) {
            #pragma unroll
            for (int it = 0; it < 8; ++it) {
                int L = it * NTHREADS + tid;
                int b = L >> 6, c = L & 63;
                ssm4[b * SQ_STRIDE + c] = __ldcg(&s4g[b * (RR / 4) + ch * 64 + c]);
            }
            __syncthreads();

            const float4* wrow = &wsm4[r_loc * WQ_STRIDE + ch * 64];
            const float4* sA4 = &ssm4[bA * SQ_STRIDE];
            const float4* sB4 = &ssm4[bB * SQ_STRIDE];

            float a = pA, b2 = pB;
            #pragma unroll 8
            for (int kq = 0; kq < 64; ++kq) {
                float4 w = wrow[kq];
                float4 sa = sA4[kq];
                float4 sb = sB4[kq];
                a = fmaf(w.x, sa.x, a);
                a = fmaf(w.y, sa.y, a);
                a = fmaf(w.z, sa.z, a);
                a = fmaf(w.w, sa.w, a);
                b2 = fmaf(w.x, sb.x, b2);
                b2 = fmaf(w.y, sb.y, b2);
                b2 = fmaf(w.z, sb.z, b2);
                b2 = fmaf(w.w, sb.w, b2);
            }
            pA = a; pB = b2;

            if (ch & 1) {   // end of a 512-float slice: fold ascending
                accA = __fadd_rn(accA, pA); pA = 0.0f;
                accB = __fadd_rn(accB, pB); pB = 0.0f;
            }
            __syncthreads();
        }

        {
            float zA = __fadd_rn(accA, uA);
            float thA = fast_tanh_B(zA);
            float snA = do_upd(soA, thA);
            out[oA] = snA;
            snxt[bA * RR + r] = snA;

            float zB = __fadd_rn(accB, uB);
            float thB = fast_tanh_B(zB);
            float snB = do_upd(soB, thB);
            out[oB] = snB;
            snxt[bB * RR + r] = snB;
        }

        __threadfence();
        __syncthreads();
        if (tid == 0) {
            atomicAdd(&g_bar, 1u);
            unsigned int target = (unsigned int)(t + 1) * NCTA;
            while (*((volatile unsigned int*)&g_bar) < target) {
                __nanosleep(40);
            }
        }
        __syncthreads();

        par ^= 1;
    }
}

// ---------------------------------------------------------------------------
extern "C" void kernel_launch(void* const* d_in, const int* in_sizes, int n_in,
                              void* d_out, int out_size) {
    const float* x      = (const float*)d_in[0];
    const float* Win    = (const float*)d_in[1];
    const float* Wrec   = (const float*)d_in[2];
    const float* bias   = (const float*)d_in[3];
    const float* state0 = (const float*)d_in[4];
    float* out = (float*)d_out;

    int smem_gemm = (32 * XS_STRIDE + 64 * WS_STRIDE4) * 16;
    int smem_rec  = (ROWS_PER_CTA * WQ_STRIDE + BB * SQ_STRIDE) * 16;

    cudaFuncSetAttribute(input_gemm_strict, cudaFuncAttributeMaxDynamicSharedMemorySize, smem_gemm);
    cudaFuncSetAttribute(recurrent_kernel, cudaFuncAttributeMaxDynamicSharedMemorySize, smem_rec);

    init_kernel<<<(BB * RR + 255) / 256, 256>>>(state0);

    input_gemm_strict<<<(BB * TT) / 32, 256, smem_gemm>>>(x, Win, bias, out);

    recurrent_kernel<<<NCTA, NTHREADS, smem_rec>>>(Wrec, out);
}

// round 14
// speedup vs baseline: 1.2567x; 1.2567x over previous
#include <cuda_runtime.h>
#include <math.h>

#define BB 32
#define TT 512
#define FF 128
#define RR 2048
#define C1 0.05f
#define C2 0.95f

#define NCTA 128
#define ROWS_PER_CTA 16
#define NTHREADS 128            // 4 warps
#define WQ 513                  // W row stride in quads (2052 words ≡ 4 mod 32)
#define SQ 65                   // staging batch-row stride in quads

__device__ float g_state[2][BB * RR];
__device__ unsigned int g_bar;

// ---------------------------------------------------------------------------
// IDENTIFIED REFERENCE RECIPE (decoded round 12, verified rel_err=0 round 13):
//   gemm: fp32 splitK=4 — 4 k-slices of 512; each slice a serial FMA chain
//         from zero, k ascending; slice partials folded by ascending fadds.
//   z = fadd(acc, u); tanh = XLA EmitFastTanh (clamp ±7.99881172180175781,
//   FMA Cephes, IEEE div); upd = fmaf(C1, s, C2*th); u = serial f-chain + bias.
// ---------------------------------------------------------------------------
__device__ __forceinline__ float fast_tanh_B(float x) {
    const float cl = 7.99881172180175781f;
    float xc = fminf(fmaxf(x, -cl), cl);
    float x2 = __fmul_rn(xc, xc);
    float p = -2.76076847742355e-16f;
    p = fmaf(x2, p, 2.00018790482477e-13f);
    p = fmaf(x2, p, -8.60467152213735e-11f);
    p = fmaf(x2, p, 5.12229709037114e-08f);
    p = fmaf(x2, p, 1.48572235717979e-05f);
    p = fmaf(x2, p, 6.37261928875436e-04f);
    p = fmaf(x2, p, 4.89352455891786e-03f);
    float num = __fmul_rn(xc, p);
    float q = 1.19825839466702e-06f;
    q = fmaf(x2, q, 1.18534705686654e-04f);
    q = fmaf(x2, q, 2.26843463243900e-03f);
    q = fmaf(x2, q, 4.89352518554385e-03f);
    float r = __fdiv_rn(num, q);
    return (fabsf(x) < 0.0004f) ? x : r;
}
__device__ __forceinline__ float do_upd(float s, float th) {
    return fmaf(C1, s, __fmul_rn(C2, th));
}

__device__ __forceinline__ unsigned smem_addr_u32(const void* p) {
    unsigned r;
    asm("{ .reg .u64 t; cvta.to.shared.u64 t, %1; cvt.u32.u64 %0, t; }"
        : "=r"(r) : "l"(p));
    return r;
}
__device__ __forceinline__ void cp_async16(unsigned dst, const void* src) {
    asm volatile("cp.async.cg.shared.global [%0], [%1], 16;"
                 :: "r"(dst), "l"(src));
}

// ---------------------------------------------------------------------------
__global__ void init_kernel(const float* __restrict__ state0) {
    int i = blockIdx.x * blockDim.x + threadIdx.x;
    if (i == 0) g_bar = 0u;
    if (i < BB * RR) g_state[0][i] = state0[i & (RR - 1)];
}

// ---------------------------------------------------------------------------
// u[bt][r] = serial FMA chain over f ascending (K=128) + b[r].
// ---------------------------------------------------------------------------
#define XS_STRIDE 33
#define WS_STRIDE4 33

__global__ void __launch_bounds__(256) input_gemm_strict(
    const float* __restrict__ x, const float* __restrict__ Win,
    const float* __restrict__ bias, float* __restrict__ out) {
    extern __shared__ float sm[];
    float4* xs4 = reinterpret_cast<float4*>(sm);
    float4* ws4 = reinterpret_cast<float4*>(sm) + 32 * XS_STRIDE;

    const int tid = threadIdx.x;
    const int bt0 = blockIdx.x * 32;

    const float4* xg4 = reinterpret_cast<const float4*>(x);
    #pragma unroll
    for (int it = 0; it < 4; ++it) {
        int L = it * 256 + tid;
        int row = L >> 5, c = L & 31;
        xs4[row * XS_STRIDE + c] = xg4[(size_t)(bt0 + row) * 32 + c];
    }

    const int btl = tid >> 3;
    const int rg = tid & 7;
    const float4* wg4 = reinterpret_cast<const float4*>(Win);

    for (int rt = 0; rt < RR; rt += 64) {
        __syncthreads();
        #pragma unroll
        for (int it = 0; it < 8; ++it) {
            int L = it * 256 + tid;
            int row = L >> 5, c = L & 31;
            ws4[row * WS_STRIDE4 + c] = wg4[(size_t)(rt + row) * 32 + c];
        }
        __syncthreads();

        float acc[8];
        #pragma unroll
        for (int j = 0; j < 8; ++j) acc[j] = 0.0f;

        #pragma unroll 8
        for (int fq = 0; fq < 32; ++fq) {
            float4 xq = xs4[btl * XS_STRIDE + fq];
            #pragma unroll
            for (int j = 0; j < 8; ++j) {
                float4 wq = ws4[(rg * 8 + j) * WS_STRIDE4 + fq];
                float a = acc[j];
                a = fmaf(xq.x, wq.x, a);
                a = fmaf(xq.y, wq.y, a);
                a = fmaf(xq.z, wq.z, a);
                a = fmaf(xq.w, wq.w, a);
                acc[j] = a;
            }
        }
        #pragma unroll
        for (int j = 0; j < 8; ++j) {
            int r = rt + rg * 8 + j;
            out[(size_t)(bt0 + btl) * RR + r] = __fadd_rn(acc[j], bias[r]);
        }
    }
}

// ---------------------------------------------------------------------------
// Persistent scan. 128 CTAs x 128 threads. Thread tile: 2 rows {rh, rh+8} x
// 2 batches {2bh, 2bh+1} = 4 outputs (4 independent chains -> ILP).
// s staged per 256-float chunk via cp.async.cg (L2-direct) double buffer.
// Slice = 512 floats = 2 chunks; fold after odd chunks (exact recipe order).
// ---------------------------------------------------------------------------
__global__ void __launch_bounds__(NTHREADS) recurrent_kernel(
    const float* __restrict__ Wrec, float* __restrict__ out) {
    extern __shared__ float4 smq[];
    float4* wsm4 = smq;                    // 16 x 513 quads
    float4* sbuf = smq + ROWS_PER_CTA * WQ; // 2 x 32 x 65 quads

    const int tid = threadIdx.x;
    const int cta = blockIdx.x;
    const int rbase = cta * ROWS_PER_CTA;

    // Load W slice once (row stride 513 quads: lanes rh=0..7 conflict-free)
    const float4* W4 = reinterpret_cast<const float4*>(Wrec);
    for (int L = tid; L < ROWS_PER_CTA * (RR / 4); L += NTHREADS) {
        int row = L >> 9, c = L & 511;
        wsm4[row * WQ + c] = W4[(size_t)(rbase + row) * (RR / 4) + c];
    }

    const int rh = tid & 7;
    const int bh = tid >> 3;           // 0..15
    const int r0 = rbase + rh, r1 = rbase + rh + 8;
    const int b0 = 2 * bh, b1 = 2 * bh + 1;
    const unsigned sbuf_base = smem_addr_u32(sbuf);

    __syncthreads();

    int par = 0;
    for (int t = 0; t < TT; ++t) {
        const float* scur = g_state[par];
        float* snxt = g_state[par ^ 1];
        const float4* s4g = reinterpret_cast<const float4*>(scur);

        // Prefetch u and s_old (latency hidden behind chunk-0 staging+compute)
        size_t o00 = ((size_t)b0 * TT + t) * RR + r0;
        size_t o01 = ((size_t)b1 * TT + t) * RR + r0;
        size_t o10 = ((size_t)b0 * TT + t) * RR + r1;
        size_t o11 = ((size_t)b1 * TT + t) * RR + r1;
        float u00 = out[o00], u01 = out[o01];
        float u10 = out[o10], u11 = out[o11];
        float so00 = __ldcg(&scur[b0 * RR + r0]);
        float so01 = __ldcg(&scur[b1 * RR + r0]);
        float so10 = __ldcg(&scur[b0 * RR + r1]);
        float so11 = __ldcg(&scur[b1 * RR + r1]);

        // Stage chunk 0 into buffer 0
        #pragma unroll
        for (int it = 0; it < 16; ++it) {
            int L = it * NTHREADS + tid;       // 0..2047
            int b = L >> 6, c = L & 63;
            unsigned dst = sbuf_base + (unsigned)(b * SQ + c) * 16u;
            cp_async16(dst, &s4g[(size_t)b * (RR / 4) + c]);
        }
        asm volatile("cp.async.commit_group;");
        asm volatile("cp.async.wait_group 0;" ::: "memory");
        __syncthreads();

        float a00 = 0.f, a01 = 0.f, a10 = 0.f, a11 = 0.f;   // folded slices
        float p00 = 0.f, p01 = 0.f, p10 = 0.f, p11 = 0.f;   // current slice

        #pragma unroll 1
        for (int ch = 0; ch < 8; ++ch) {
            const int cur = ch & 1;
            if (ch < 7) {   // prefetch next chunk into other buffer
                const int nb = cur ^ 1;
                #pragma unroll
                for (int it = 0; it < 16; ++it) {
                    int L = it * NTHREADS + tid;
                    int b = L >> 6, c = L & 63;
                    unsigned dst = sbuf_base +
                        (unsigned)(nb * 32 * SQ + b * SQ + c) * 16u;
                    cp_async16(dst, &s4g[(size_t)b * (RR / 4) + (ch + 1) * 64 + c]);
                }
                asm volatile("cp.async.commit_group;");
            }

            const float4* wr0 = wsm4 + rh * WQ + ch * 64;
            const float4* wr1 = wsm4 + (rh + 8) * WQ + ch * 64;
            const float4* sb0 = sbuf + cur * 32 * SQ + b0 * SQ;
            const float4* sb1 = sb0 + SQ;

            #pragma unroll 4
            for (int kq = 0; kq < 64; ++kq) {
                float4 w0 = wr0[kq];
                float4 w1 = wr1[kq];
                float4 s0 = sb0[kq];
                float4 s1 = sb1[kq];
                p00 = fmaf(w0.x, s0.x, p00);
                p00 = fmaf(w0.y, s0.y, p00);
                p00 = fmaf(w0.z, s0.z, p00);
                p00 = fmaf(w0.w, s0.w, p00);
                p01 = fmaf(w0.x, s1.x, p01);
                p01 = fmaf(w0.y, s1.y, p01);
                p01 = fmaf(w0.z, s1.z, p01);
                p01 = fmaf(w0.w, s1.w, p01);
                p10 = fmaf(w1.x, s0.x, p10);
                p10 = fmaf(w1.y, s0.y, p10);
                p10 = fmaf(w1.z, s0.z, p10);
                p10 = fmaf(w1.w, s0.w, p10);
                p11 = fmaf(w1.x, s1.x, p11);
                p11 = fmaf(w1.y, s1.y, p11);
                p11 = fmaf(w1.z, s1.z, p11);
                p11 = fmaf(w1.w, s1.w, p11);
            }

            if (ch & 1) {    // end of 512-float slice: ascending fold
                a00 = __fadd_rn(a00, p00); p00 = 0.f;
                a01 = __fadd_rn(a01, p01); p01 = 0.f;
                a10 = __fadd_rn(a10, p10); p10 = 0.f;
                a11 = __fadd_rn(a11, p11); p11 = 0.f;
            }

            asm volatile("cp.async.wait_group 0;" ::: "memory");
            __syncthreads();
        }

        // Epilogue (exact recipe per output)
        {
            float z, th, sn;
            z = __fadd_rn(a00, u00); th = fast_tanh_B(z); sn = do_upd(so00, th);
            out[o00] = sn; snxt[b0 * RR + r0] = sn;
            z = __fadd_rn(a01, u01); th = fast_tanh_B(z); sn = do_upd(so01, th);
            out[o01] = sn; snxt[b1 * RR + r0] = sn;
            z = __fadd_rn(a10, u10); th = fast_tanh_B(z); sn = do_upd(so10, th);
            out[o10] = sn; snxt[b0 * RR + r1] = sn;
            z = __fadd_rn(a11, u11); th = fast_tanh_B(z); sn = do_upd(so11, th);
            out[o11] = sn; snxt[b1 * RR + r1] = sn;
        }

        __threadfence();
        __syncthreads();
        if (tid == 0) {
            atomicAdd(&g_bar, 1u);
            unsigned int target = (unsigned int)(t + 1) * NCTA;
            while (*((volatile unsigned int*)&g_bar) < target) {
                __nanosleep(32);
            }
        }
        __syncthreads();

        par ^= 1;
    }
}

// ---------------------------------------------------------------------------
extern "C" void kernel_launch(void* const* d_in, const int* in_sizes, int n_in,
                              void* d_out, int out_size) {
    const float* x      = (const float*)d_in[0];
    const float* Win    = (const float*)d_in[1];
    const float* Wrec   = (const float*)d_in[2];
    const float* bias   = (const float*)d_in[3];
    const float* state0 = (const float*)d_in[4];
    float* out = (float*)d_out;

    int smem_gemm = (32 * XS_STRIDE + 64 * WS_STRIDE4) * 16;
    int smem_rec  = (ROWS_PER_CTA * WQ + 2 * 32 * SQ) * 16;   // ~197.9 KB

    cudaFuncSetAttribute(input_gemm_strict, cudaFuncAttributeMaxDynamicSharedMemorySize, smem_gemm);
    cudaFuncSetAttribute(recurrent_kernel, cudaFuncAttributeMaxDynamicSharedMemorySize, smem_rec);

    init_kernel<<<(BB * RR + 255) / 256, 256>>>(state0);

    input_gemm_strict<<<(BB * TT) / 32, 256, smem_gemm>>>(x, Win, bias, out);

    recurrent_kernel<<<NCTA, NTHREADS, smem_rec>>>(Wrec, out);
}

// round 15
// speedup vs baseline: 1.3513x; 1.0753x over previous
#include <cuda_runtime.h>
#include <math.h>

#define BB 32
#define TT 512
#define FF 128
#define RR 2048
#define C1 0.05f
#define C2 0.95f

#define NCTA 128
#define ROWS_PER_CTA 16
#define NTHREADS 128            // 4 warps, 1 per SMSP
#define WQ 513                  // W row stride in quads (2052 words ≡ 4 mod 32)
#define SQ 65                   // staging batch-row stride in quads

__device__ float g_state[2][BB * RR];
__device__ unsigned int g_bar;

// ---------------------------------------------------------------------------
// IDENTIFIED REFERENCE RECIPE (verified rel_err = 0.0):
//   gemm: fp32 splitK=4 — 4 k-slices of 512; each slice a serial FMA chain
//         from zero, k ascending; slice partials folded by ascending fadds.
//   z = fadd(acc, u); tanh = XLA EmitFastTanh (clamp ±7.99881172180175781,
//   FMA Cephes, IEEE div); upd = fmaf(C1, s, C2*th); u = serial f-chain + bias.
// ---------------------------------------------------------------------------
__device__ __forceinline__ float fast_tanh_B(float x) {
    const float cl = 7.99881172180175781f;
    float xc = fminf(fmaxf(x, -cl), cl);
    float x2 = __fmul_rn(xc, xc);
    float p = -2.76076847742355e-16f;
    p = fmaf(x2, p, 2.00018790482477e-13f);
    p = fmaf(x2, p, -8.60467152213735e-11f);
    p = fmaf(x2, p, 5.12229709037114e-08f);
    p = fmaf(x2, p, 1.48572235717979e-05f);
    p = fmaf(x2, p, 6.37261928875436e-04f);
    p = fmaf(x2, p, 4.89352455891786e-03f);
    float num = __fmul_rn(xc, p);
    float q = 1.19825839466702e-06f;
    q = fmaf(x2, q, 1.18534705686654e-04f);
    q = fmaf(x2, q, 2.26843463243900e-03f);
    q = fmaf(x2, q, 4.89352518554385e-03f);
    float r = __fdiv_rn(num, q);
    return (fabsf(x) < 0.0004f) ? x : r;
}
__device__ __forceinline__ float do_upd(float s, float th) {
    return fmaf(C1, s, __fmul_rn(C2, th));
}

__device__ __forceinline__ unsigned smem_addr_u32(const void* p) {
    unsigned r;
    asm("{ .reg .u64 t; cvta.to.shared.u64 t, %1; cvt.u32.u64 %0, t; }"
        : "=r"(r) : "l"(p));
    return r;
}
__device__ __forceinline__ void cp_async16(unsigned dst, const void* src) {
    asm volatile("cp.async.cg.shared.global [%0], [%1], 16;"
                 :: "r"(dst), "l"(src));
}

// ---------------------------------------------------------------------------
// Fused init + u projection. Each of 512 blocks also initializes its 128-float
// slice of g_state[0]; block 0 resets the grid-barrier counter.
// u[bt][r] = serial FMA chain over f ascending (K=128) + b[r].
// ---------------------------------------------------------------------------
#define XS_STRIDE 33
#define WS_STRIDE4 33

__global__ void __launch_bounds__(256) input_gemm_strict(
    const float* __restrict__ x, const float* __restrict__ Win,
    const float* __restrict__ bias, const float* __restrict__ state0,
    float* __restrict__ out) {
    extern __shared__ float sm[];
    float4* xs4 = reinterpret_cast<float4*>(sm);
    float4* ws4 = reinterpret_cast<float4*>(sm) + 32 * XS_STRIDE;

    const int tid = threadIdx.x;
    const int bt0 = blockIdx.x * 32;

    // merged init: this block's slice of state + barrier reset
    if (blockIdx.x == 0 && tid == 0) g_bar = 0u;
    {
        int idx = blockIdx.x * 128 + tid;
        if (tid < 128) g_state[0][idx] = state0[idx & (RR - 1)];
    }

    const float4* xg4 = reinterpret_cast<const float4*>(x);
    #pragma unroll
    for (int it = 0; it < 4; ++it) {
        int L = it * 256 + tid;
        int row = L >> 5, c = L & 31;
        xs4[row * XS_STRIDE + c] = xg4[(size_t)(bt0 + row) * 32 + c];
    }

    const int btl = tid >> 3;
    const int rg = tid & 7;
    const float4* wg4 = reinterpret_cast<const float4*>(Win);

    for (int rt = 0; rt < RR; rt += 64) {
        __syncthreads();
        #pragma unroll
        for (int it = 0; it < 8; ++it) {
            int L = it * 256 + tid;
            int row = L >> 5, c = L & 31;
            ws4[row * WS_STRIDE4 + c] = wg4[(size_t)(rt + row) * 32 + c];
        }
        __syncthreads();

        float acc[8];
        #pragma unroll
        for (int j = 0; j < 8; ++j) acc[j] = 0.0f;

        #pragma unroll 8
        for (int fq = 0; fq < 32; ++fq) {
            float4 xq = xs4[btl * XS_STRIDE + fq];
            #pragma unroll
            for (int j = 0; j < 8; ++j) {
                float4 wq = ws4[(rg * 8 + j) * WS_STRIDE4 + fq];
                float a = acc[j];
                a = fmaf(xq.x, wq.x, a);
                a = fmaf(xq.y, wq.y, a);
                a = fmaf(xq.z, wq.z, a);
                a = fmaf(xq.w, wq.w, a);
                acc[j] = a;
            }
        }
        #pragma unroll
        for (int j = 0; j < 8; ++j) {
            int r = rt + rg * 8 + j;
            out[(size_t)(bt0 + btl) * RR + r] = __fadd_rn(acc[j], bias[r]);
        }
    }
}

// ---------------------------------------------------------------------------
// Persistent scan. 128 CTAs x 128 threads. Thread tile: 2 rows {rh, rh+8} x
// 2 batches {2bh, 2bh+1}. Warp w stages ONLY batches 8w..8w+7 (the ones its
// lanes consume) -> chunk loop needs only __syncwarp, never __syncthreads.
// Slice = 512 floats = 2 chunks; fold after odd chunks (exact recipe order).
// ---------------------------------------------------------------------------
__global__ void __launch_bounds__(NTHREADS) recurrent_kernel(
    const float* __restrict__ Wrec, float* __restrict__ out) {
    extern __shared__ float4 smq[];
    float4* wsm4 = smq;                      // 16 x 513 quads
    float4* sbuf = smq + ROWS_PER_CTA * WQ;  // 2 x 32 x 65 quads

    const int tid = threadIdx.x;
    const int lane = tid & 31;
    const int warp = tid >> 5;
    const int cta = blockIdx.x;
    const int rbase = cta * ROWS_PER_CTA;

    const float4* W4 = reinterpret_cast<const float4*>(Wrec);
    for (int L = tid; L < ROWS_PER_CTA * (RR / 4); L += NTHREADS) {
        int row = L >> 9, c = L & 511;
        wsm4[row * WQ + c] = W4[(size_t)(rbase + row) * (RR / 4) + c];
    }

    const int rh = tid & 7;
    const int bh = tid >> 3;           // 0..15
    const int r0 = rbase + rh, r1 = rbase + rh + 8;
    const int b0 = 2 * bh, b1 = 2 * bh + 1;
    const int wb = warp * 8;           // this warp's first staged batch
    const unsigned sbuf_base = smem_addr_u32(sbuf);

    __syncthreads();   // W visible

    int par = 0;
    for (int t = 0; t < TT; ++t) {
        const float* scur = g_state[par];
        float* snxt = g_state[par ^ 1];
        const float4* s4g = reinterpret_cast<const float4*>(scur);

        // Prefetch u and s_old (consumed only in the epilogue)
        size_t o00 = ((size_t)b0 * TT + t) * RR + r0;
        size_t o01 = ((size_t)b1 * TT + t) * RR + r0;
        size_t o10 = ((size_t)b0 * TT + t) * RR + r1;
        size_t o11 = ((size_t)b1 * TT + t) * RR + r1;
        float u00 = out[o00], u01 = out[o01];
        float u10 = out[o10], u11 = out[o11];
        float so00 = __ldcg(&scur[b0 * RR + r0]);
        float so01 = __ldcg(&scur[b1 * RR + r0]);
        float so10 = __ldcg(&scur[b0 * RR + r1]);
        float so11 = __ldcg(&scur[b1 * RR + r1]);

        // Stage chunk 0 (warp-private batches) into buffer 0
        #pragma unroll
        for (int it = 0; it < 16; ++it) {
            int L = it * 32 + lane;            // 0..511
            int b = wb + (L >> 6), c = L & 63;
            unsigned dst = sbuf_base + (unsigned)(b * SQ + c) * 16u;
            cp_async16(dst, &s4g[(size_t)b * (RR / 4) + c]);
        }
        asm volatile("cp.async.commit_group;");
        asm volatile("cp.async.wait_group 0;" ::: "memory");
        __syncwarp();

        float a00 = 0.f, a01 = 0.f, a10 = 0.f, a11 = 0.f;   // folded slices
        float p00 = 0.f, p01 = 0.f, p10 = 0.f, p11 = 0.f;   // current slice

        #pragma unroll 1
        for (int ch = 0; ch < 8; ++ch) {
            const int cur = ch & 1;
            if (ch < 7) {   // prefetch next chunk into the other buffer
                const int nb = cur ^ 1;
                #pragma unroll
                for (int it = 0; it < 16; ++it) {
                    int L = it * 32 + lane;
                    int b = wb + (L >> 6), c = L & 63;
                    unsigned dst = sbuf_base +
                        (unsigned)(nb * 32 * SQ + b * SQ + c) * 16u;
                    cp_async16(dst, &s4g[(size_t)b * (RR / 4) + (ch + 1) * 64 + c]);
                }
                asm volatile("cp.async.commit_group;");
            }

            const float4* wr0 = wsm4 + rh * WQ + ch * 64;
            const float4* wr1 = wsm4 + (rh + 8) * WQ + ch * 64;
            const float4* sb0 = sbuf + cur * 32 * SQ + b0 * SQ;
            const float4* sb1 = sb0 + SQ;

            #pragma unroll 4
            for (int kq = 0; kq < 64; ++kq) {
                float4 w0 = wr0[kq];
                float4 w1 = wr1[kq];
                float4 s0 = sb0[kq];
                float4 s1 = sb1[kq];
                p00 = fmaf(w0.x, s0.x, p00);
                p00 = fmaf(w0.y, s0.y, p00);
                p00 = fmaf(w0.z, s0.z, p00);
                p00 = fmaf(w0.w, s0.w, p00);
                p01 = fmaf(w0.x, s1.x, p01);
                p01 = fmaf(w0.y, s1.y, p01);
                p01 = fmaf(w0.z, s1.z, p01);
                p01 = fmaf(w0.w, s1.w, p01);
                p10 = fmaf(w1.x, s0.x, p10);
                p10 = fmaf(w1.y, s0.y, p10);
                p10 = fmaf(w1.z, s0.z, p10);
                p10 = fmaf(w1.w, s0.w, p10);
                p11 = fmaf(w1.x, s1.x, p11);
                p11 = fmaf(w1.y, s1.y, p11);
                p11 = fmaf(w1.z, s1.z, p11);
                p11 = fmaf(w1.w, s1.w, p11);
            }

            if (ch & 1) {    // end of 512-float slice: ascending fold
                a00 = __fadd_rn(a00, p00); p00 = 0.f;
                a01 = __fadd_rn(a01, p01); p01 = 0.f;
                a10 = __fadd_rn(a10, p10); p10 = 0.f;
                a11 = __fadd_rn(a11, p11); p11 = 0.f;
            }

            asm volatile("cp.async.wait_group 0;" ::: "memory");
            __syncwarp();
        }

        // Epilogue (exact recipe per output)
        {
            float z, th, sn;
            z = __fadd_rn(a00, u00); th = fast_tanh_B(z); sn = do_upd(so00, th);
            out[o00] = sn; snxt[b0 * RR + r0] = sn;
            z = __fadd_rn(a01, u01); th = fast_tanh_B(z); sn = do_upd(so01, th);
            out[o01] = sn; snxt[b1 * RR + r0] = sn;
            z = __fadd_rn(a10, u10); th = fast_tanh_B(z); sn = do_upd(so10, th);
            out[o10] = sn; snxt[b0 * RR + r1] = sn;
            z = __fadd_rn(a11, u11); th = fast_tanh_B(z); sn = do_upd(so11, th);
            out[o11] = sn; snxt[b1 * RR + r1] = sn;
        }

        // Grid barrier: bar.sync orders the CTA's writes, tid0 publishes with
        // a release-atomic, spins with acquire loads (CG grid.sync pattern).
        __syncthreads();
        if (tid == 0) {
            asm volatile("red.release.gpu.global.add.u32 [%0], %1;"
                         :: "l"(&g_bar), "r"(1u) : "memory");
            unsigned target = (unsigned)(t + 1) * NCTA;
            unsigned v;
            do {
                asm volatile("ld.acquire.gpu.global.u32 %0, [%1];"
                             : "=r"(v) : "l"(&g_bar) : "memory");
                if (v >= target) break;
                __nanosleep(24);
            } while (true);
        }
        __syncthreads();

        par ^= 1;
    }
}

// ---------------------------------------------------------------------------
extern "C" void kernel_launch(void* const* d_in, const int* in_sizes, int n_in,
                              void* d_out, int out_size) {
    const float* x      = (const float*)d_in[0];
    const float* Win    = (const float*)d_in[1];
    const float* Wrec   = (const float*)d_in[2];
    const float* bias   = (const float*)d_in[3];
    const float* state0 = (const float*)d_in[4];
    float* out = (float*)d_out;

    int smem_gemm = (32 * XS_STRIDE + 64 * WS_STRIDE4) * 16;
    int smem_rec  = (ROWS_PER_CTA * WQ + 2 * 32 * SQ) * 16;   // ~197.9 KB

    cudaFuncSetAttribute(input_gemm_strict, cudaFuncAttributeMaxDynamicSharedMemorySize, smem_gemm);
    cudaFuncSetAttribute(recurrent_kernel, cudaFuncAttributeMaxDynamicSharedMemorySize, smem_rec);

    input_gemm_strict<<<(BB * TT) / 32, 256, smem_gemm>>>(x, Win, bias, state0, out);

    recurrent_kernel<<<NCTA, NTHREADS, smem_rec>>>(Wrec, out);
}